// round 6
// baseline (speedup 1.0000x reference)
#include <cuda_runtime.h>
#include <math.h>

#define NMAX 100000
#define EMAX 1600000
#define SCAN_B 1024
#define NBLK ((NMAX + SCAN_B - 1) / SCAN_B)   // 98

// Scratch (__device__ globals; no allocation allowed)
__device__ int   g_cnt[NMAX];
__device__ float g_dinv[NMAX];
__device__ int   g_rowstart[NMAX + 1];
__device__ int   g_fill[NMAX];
__device__ int   g_bsum[NBLK + 1];
__device__ int2  g_csr[EMAX];          // packed (src, norm-as-int)
__device__ float g_a[NMAX * 64];
__device__ float g_b[NMAX * 64];

// ---------------------------------------------------------------------------
__global__ void zero_cnt_kernel(int n) {
    int i = blockIdx.x * blockDim.x + threadIdx.x;
    if (i < n) g_cnt[i] = 0;
}

__global__ void count_kernel(const int* __restrict__ dst, int E) {
    int i = blockIdx.x * blockDim.x + threadIdx.x;
    if (i < E) atomicAdd(&g_cnt[dst[i]], 1);
}

__global__ void dinv_kernel(int n) {
    int i = blockIdx.x * blockDim.x + threadIdx.x;
    if (i < n) g_dinv[i] = rsqrtf((float)g_cnt[i] + 1.0f);  // +1 self loop
}

// ---------------------------------------------------------------------------
// Grid-wide exclusive scan of g_cnt -> g_rowstart (3 passes)
// ---------------------------------------------------------------------------
__global__ void scan_local_kernel(int n) {
    __shared__ int sm[SCAN_B];
    int t = threadIdx.x;
    int i = blockIdx.x * SCAN_B + t;
    int v = (i < n) ? g_cnt[i] : 0;
    sm[t] = v;
    __syncthreads();
    #pragma unroll
    for (int off = 1; off < SCAN_B; off <<= 1) {
        int u = (t >= off) ? sm[t - off] : 0;
        __syncthreads();
        sm[t] += u;
        __syncthreads();
    }
    if (i < n) g_rowstart[i] = sm[t] - v;
    if (t == SCAN_B - 1) g_bsum[blockIdx.x] = sm[t];
}

__global__ void scan_bsums_kernel(int nb) {
    __shared__ int sm[128];
    int t = threadIdx.x;
    int v = (t < nb) ? g_bsum[t] : 0;
    sm[t] = v;
    __syncthreads();
    #pragma unroll
    for (int off = 1; off < 128; off <<= 1) {
        int u = (t >= off) ? sm[t - off] : 0;
        __syncthreads();
        sm[t] += u;
        __syncthreads();
    }
    if (t < nb) g_bsum[t] = sm[t] - v;
}

__global__ void scan_apply_kernel(int n, int E) {
    int i = blockIdx.x * blockDim.x + threadIdx.x;
    if (i < n) {
        int r = g_rowstart[i] + g_bsum[i / SCAN_B];
        g_rowstart[i] = r;
        g_fill[i] = r;
    }
    if (i == 0) g_rowstart[n] = E;
}

__global__ void fill_kernel(const int* __restrict__ src,
                            const int* __restrict__ dst, int E) {
    int e = blockIdx.x * blockDim.x + threadIdx.x;
    if (e >= E) return;
    int s = src[e], d = dst[e];
    float nrm = g_dinv[s] * g_dinv[d];
    int pos = atomicAdd(&g_fill[d], 1);
    g_csr[pos] = make_int2(s, __float_as_int(nrm));
}

// ---------------------------------------------------------------------------
// Fused GCN layer: y[i] = relu( (dinv_i^2 * x_i + sum_j nrm_ij x_j) @ W + b )
// One warp per node. Aggregation: float4 per lane, half-warp per neighbor
// (lanes 0-15 -> neighbor j, lanes 16-31 -> neighbor j+1), unrolled x2 so
// 4 neighbor rows are in flight per warp. Halves combined via shfl_xor(16).
// ---------------------------------------------------------------------------
__global__ void layer_kernel(const float* __restrict__ Xext, int xsel,
                             const float* __restrict__ W,
                             const float* __restrict__ bias,
                             int osel, int n)
{
    __shared__ float Ws[64 * 64];
    int tid = threadIdx.x;
    for (int i = tid; i < 64 * 64; i += 256) Ws[i] = W[i];

    const float* X = (xsel < 0) ? Xext : (xsel == 0 ? g_a : g_b);
    float* Y = (osel == 0) ? g_a : g_b;
    __syncthreads();

    int warp = tid >> 5, lane = tid & 31;
    int node = blockIdx.x * 8 + warp;
    if (node >= n) return;

    const float4* X4 = (const float4*)X;
    int half = lane >> 4;       // 0 or 1
    int l16  = lane & 15;       // float4 index within row

    float ax = 0.0f, ay = 0.0f, az = 0.0f, aw = 0.0f;

    int beg = g_rowstart[node], end = g_rowstart[node + 1];
    int j = beg + half;
    // 2 neighbors per half-warp per iteration (4 rows in flight per warp)
    for (; j + 2 < end; j += 4) {
        int2 e0 = g_csr[j];
        int2 e1 = g_csr[j + 2];
        float4 v0 = X4[(size_t)e0.x * 16 + l16];
        float4 v1 = X4[(size_t)e1.x * 16 + l16];
        float n0 = __int_as_float(e0.y);
        float n1 = __int_as_float(e1.y);
        ax = fmaf(n0, v0.x, ax); ay = fmaf(n0, v0.y, ay);
        az = fmaf(n0, v0.z, az); aw = fmaf(n0, v0.w, aw);
        ax = fmaf(n1, v1.x, ax); ay = fmaf(n1, v1.y, ay);
        az = fmaf(n1, v1.z, az); aw = fmaf(n1, v1.w, aw);
    }
    if (j < end) {
        int2 e = g_csr[j];
        float4 v = X4[(size_t)e.x * 16 + l16];
        float nm = __int_as_float(e.y);
        ax = fmaf(nm, v.x, ax); ay = fmaf(nm, v.y, ay);
        az = fmaf(nm, v.z, az); aw = fmaf(nm, v.w, aw);
    }

    // Self loop (add once, in lower half only, pre-combine)
    if (half == 0) {
        float di = g_dinv[node];
        float d2 = di * di;
        float4 xx = X4[(size_t)node * 16 + l16];
        ax = fmaf(d2, xx.x, ax); ay = fmaf(d2, xx.y, ay);
        az = fmaf(d2, xx.z, az); aw = fmaf(d2, xx.w, aw);
    }

    // Combine half-warp partials: every lane now holds the full sum
    ax += __shfl_xor_sync(0xffffffffu, ax, 16);
    ay += __shfl_xor_sync(0xffffffffu, ay, 16);
    az += __shfl_xor_sync(0xffffffffu, az, 16);
    aw += __shfl_xor_sync(0xffffffffu, aw, 16);

    // Transform: y[c] = sum_k agg[k] * W[k][c], c = lane, lane+32.
    // Lane l16 holds features 4*l16 .. 4*l16+3 (duplicated across halves).
    float y0 = bias[lane];
    float y1 = bias[lane + 32];
    #pragma unroll
    for (int kk = 0; kk < 16; kk++) {
        float vx = __shfl_sync(0xffffffffu, ax, kk);
        float vy = __shfl_sync(0xffffffffu, ay, kk);
        float vz = __shfl_sync(0xffffffffu, az, kk);
        float vw = __shfl_sync(0xffffffffu, aw, kk);
        y0 = fmaf(vx, Ws[(4 * kk    ) * 64 + lane], y0);
        y0 = fmaf(vy, Ws[(4 * kk + 1) * 64 + lane], y0);
        y0 = fmaf(vz, Ws[(4 * kk + 2) * 64 + lane], y0);
        y0 = fmaf(vw, Ws[(4 * kk + 3) * 64 + lane], y0);
        y1 = fmaf(vx, Ws[(4 * kk    ) * 64 + 32 + lane], y1);
        y1 = fmaf(vy, Ws[(4 * kk + 1) * 64 + 32 + lane], y1);
        y1 = fmaf(vz, Ws[(4 * kk + 2) * 64 + 32 + lane], y1);
        y1 = fmaf(vw, Ws[(4 * kk + 3) * 64 + 32 + lane], y1);
    }
    y0 = fmaxf(y0, 0.0f);
    y1 = fmaxf(y1, 0.0f);
    Y[(size_t)node * 64 + lane]      = y0;
    Y[(size_t)node * 64 + 32 + lane] = y1;
}

// ---------------------------------------------------------------------------
// MLP head + log_softmax. One warp per node. Input g_a (already relu'd).
// ---------------------------------------------------------------------------
__global__ void mlp_head_kernel(const float* __restrict__ Wp1,
                                const float* __restrict__ bp1,
                                const float* __restrict__ Wp2,
                                const float* __restrict__ bp2,
                                float* __restrict__ out, int n)
{
    __shared__ float W1s[64 * 32];
    __shared__ float W2s[32 * 40];
    __shared__ float b1s[32];
    __shared__ float b2s[40];

    int tid = threadIdx.x;
    for (int i = tid; i < 64 * 32; i += 256) W1s[i] = Wp1[i];
    for (int i = tid; i < 32 * 40; i += 256) W2s[i] = Wp2[i];
    if (tid < 32) b1s[tid] = bp1[tid];
    if (tid < 40) b2s[tid] = bp2[tid];
    __syncthreads();

    int warp = tid >> 5, lane = tid & 31;
    int node = blockIdx.x * 8 + warp;
    if (node >= n) return;

    const float2* A2 = (const float2*)g_a;
    float2 xp = A2[(size_t)node * 32 + lane];   // features 2*lane, 2*lane+1

    float h = b1s[lane];
    #pragma unroll
    for (int k = 0; k < 32; k++) {
        float xk0 = __shfl_sync(0xffffffffu, xp.x, k);
        float xk1 = __shfl_sync(0xffffffffu, xp.y, k);
        h = fmaf(xk0, W1s[(2 * k    ) * 32 + lane], h);
        h = fmaf(xk1, W1s[(2 * k + 1) * 32 + lane], h);
    }
    h = fmaxf(h, 0.0f);

    float o0 = b2s[lane];
    float o1 = (lane < 8) ? b2s[32 + lane] : 0.0f;
    #pragma unroll
    for (int j = 0; j < 32; j++) {
        float hj = __shfl_sync(0xffffffffu, h, j);
        o0 = fmaf(hj, W2s[j * 40 + lane], o0);
        if (lane < 8) o1 = fmaf(hj, W2s[j * 40 + 32 + lane], o1);
    }

    float m = (lane < 8) ? fmaxf(o0, o1) : o0;
    #pragma unroll
    for (int off = 16; off; off >>= 1)
        m = fmaxf(m, __shfl_xor_sync(0xffffffffu, m, off));

    float sum = expf(o0 - m) + ((lane < 8) ? expf(o1 - m) : 0.0f);
    #pragma unroll
    for (int off = 16; off; off >>= 1)
        sum += __shfl_xor_sync(0xffffffffu, sum, off);

    float lse = m + logf(sum);

    out[(size_t)node * 40 + lane] = o0 - lse;
    if (lane < 8)
        out[(size_t)node * 40 + 32 + lane] = o1 - lse;
}

// ---------------------------------------------------------------------------
extern "C" void kernel_launch(void* const* d_in, const int* in_sizes, int n_in,
                              void* d_out, int out_size)
{
    const float* x   = (const float*)d_in[0];
    const int*   ei  = (const int*)  d_in[1];
    const float* W0  = (const float*)d_in[3];
    const float* b0  = (const float*)d_in[4];
    const float* W1  = (const float*)d_in[5];
    const float* b1  = (const float*)d_in[6];
    const float* W2  = (const float*)d_in[7];
    const float* b2  = (const float*)d_in[8];
    const float* Wp1 = (const float*)d_in[9];
    const float* bp1 = (const float*)d_in[10];
    const float* Wp2 = (const float*)d_in[11];
    const float* bp2 = (const float*)d_in[12];
    float* out = (float*)d_out;

    int n = in_sizes[0] / 64;
    int E = in_sizes[1] / 2;
    const int* src = ei;
    const int* dst = ei + E;

    int nb   = (n + 255) / 256;
    int eb   = (E + 255) / 256;
    int lay  = (n + 7) / 8;
    int nb2  = (n + SCAN_B - 1) / SCAN_B;

    // CSR build
    zero_cnt_kernel  <<<nb, 256>>>(n);
    count_kernel     <<<eb, 256>>>(dst, E);
    dinv_kernel      <<<nb, 256>>>(n);
    scan_local_kernel<<<nb2, SCAN_B>>>(n);
    scan_bsums_kernel<<<1, 128>>>(nb2);
    scan_apply_kernel<<<nb2, SCAN_B>>>(n, E);
    fill_kernel      <<<eb, 256>>>(src, dst, E);

    // Fused GCN layers (aggregate-then-transform)
    layer_kernel<<<lay, 256>>>(x,       -1, W0, b0, /*osel=*/0, n);
    layer_kernel<<<lay, 256>>>(nullptr,  0, W1, b1, /*osel=*/1, n);
    layer_kernel<<<lay, 256>>>(nullptr,  1, W2, b2, /*osel=*/0, n);

    // Head
    mlp_head_kernel<<<lay, 256>>>(Wp1, bp1, Wp2, bp2, out, n);
}